// round 9
// baseline (speedup 1.0000x reference)
#include <cuda_runtime.h>
#include <math.h>

// ---------------------------------------------------------------------------
// Problem dims (fixed by dataset): V=1024, E=256, H=512, B=64, S=2048
// ---------------------------------------------------------------------------
constexpr int Sn = 2048;
constexpr int Bn = 64;
constexpr int Hn = 512;
constexpr int En = 256;
constexpr int Vn = 1024;

constexpr int SCAN_CTAS = 128;                 // 2 batch halves x 64 j-groups
constexpr int SEQ_ELEMS = Sn * Bn * Hn;        // 67,108,864 floats (256 MB)
constexpr int SCAN_SMEM = (8 * 516 + 32 * 516) * 4;  // 82,560 B dynamic smem

// Device-global scratch (allocation-free per harness rules)
__device__ float        g_T[Vn * Hn];          // emb @ Wxh0^T + bxh0 + bhh0
__device__ float        g_seq0[SEQ_ELEMS];     // h0 sequence, reused as h1 seq
__device__ float        g_A1[SEQ_ELEMS];       // layer-1 precomputed input term
__device__ float        g_hping[2 * Bn * Hn];  // ping-pong hidden state
__device__ unsigned int g_bar;                 // grid-barrier counter

// ---------------------------------------------------------------------------
// Init: reset barrier counter + zero hidden-state ping-pong (every replay)
// ---------------------------------------------------------------------------
__global__ void scan_init() {
    unsigned i = blockIdx.x * blockDim.x + threadIdx.x;
    if (i == 0) g_bar = 0u;
    for (unsigned k = i; k < 2u * Bn * Hn; k += gridDim.x * blockDim.x)
        g_hping[k] = 0.0f;
}

// ---------------------------------------------------------------------------
// T[v][j] = sum_e emb[v][e] * Wxh0[j][e] + bxh0[j] + bhh0[j]
// One block per vocab row v; emb row staged in smem; 2 j's per thread.
// ---------------------------------------------------------------------------
__global__ void __launch_bounds__(256) build_table(
    const float* __restrict__ emb, const float* __restrict__ Wxh0,
    const float* __restrict__ bxh0, const float* __restrict__ bhh0)
{
    __shared__ float es[En];
    const int v = blockIdx.x;
    const int tid = threadIdx.x;
    es[tid] = emb[(size_t)v * En + tid];
    __syncthreads();
    #pragma unroll
    for (int jj = 0; jj < 2; jj++) {
        const int j = tid + jj * 256;
        const float4* w = (const float4*)(Wxh0 + (size_t)j * En);
        float s = 0.0f;
        #pragma unroll 16
        for (int k = 0; k < En / 4; k++) {
            float4 wv = __ldg(&w[k]);
            s = fmaf(wv.x, es[4 * k + 0], s);
            s = fmaf(wv.y, es[4 * k + 1], s);
            s = fmaf(wv.z, es[4 * k + 2], s);
            s = fmaf(wv.w, es[4 * k + 3], s);
        }
        g_T[(size_t)v * Hn + j] = s + bxh0[j] + bhh0[j];
    }
}

// ---------------------------------------------------------------------------
// Persistent recurrent scan (one launch per layer, 128 co-resident CTAs).
//   mode 0: base = T[x[b,t]][j]      (layer 0; biases folded into T)
//   mode 1: base = A1[t][b][j]       (layer 1; biases folded into A1)
//   h_t = tanh(base + h_{t-1} @ Whh^T)
// CTA c owns batch half (c&1)*32 and output cols j0=(c>>1)*8.
// Its 8 Whh rows stay in smem for the whole scan. h is exchanged through a
// global ping-pong buffer (__ldcg reads bypass stale L1), with a monotonic
// atomic-counter grid barrier per step.
// ---------------------------------------------------------------------------
__global__ void __launch_bounds__(256, 1) rnn_scan(
    const float* __restrict__ Whh,     // [512][512] (out j, in k)
    int mode,
    const int*   __restrict__ x,       // [B][S]      (mode 0)
    const float* __restrict__ T,       // [V][H]      (mode 0)
    const float* __restrict__ A1,      // [S][B][H]   (mode 1)
    float* __restrict__ hseq,          // [S][B][H]   output sequence
    float* __restrict__ hfinal)        // [B][H]      final state
{
    extern __shared__ float sm[];
    float* Ws = sm;                    // [8][516] padded
    float* hs = sm + 8 * 516;          // [32][516] padded

    const int c   = blockIdx.x;
    const int b0  = (c & 1) * 32;
    const int j0  = (c >> 1) * 8;
    const int tid = threadIdx.x;
    const int bi  = tid >> 3;          // 0..31 local batch row
    const int jj  = tid & 7;           // 0..7  local output col
    const int b   = b0 + bi;
    const int j   = j0 + jj;

    // Load this CTA's 8 Whh rows once (resident for all 2048 steps)
    for (int i = tid; i < 8 * Hn; i += 256) {
        const int r = i >> 9;
        const int k = i & 511;
        Ws[r * 516 + k] = Whh[(size_t)(j0 + r) * Hn + k];
    }

    for (int t = 0; t < Sn; t++) {
        // Stage this batch half's h_{t-1} (64 KB) into smem, L2-fresh
        const float* hsrc = g_hping + (size_t)(t & 1) * (Bn * Hn)
                                    + (size_t)b0 * Hn;
        #pragma unroll
        for (int l = 0; l < 16; l++) {
            const int i   = tid + l * 256;        // 0..4095 float4 slots
            const int row = i >> 7;               // 128 float4 per row
            const int c4  = (i & 127) << 2;
            float4 v = __ldcg((const float4*)(hsrc + row * Hn + c4));
            *(float4*)(hs + row * 516 + c4) = v;
        }
        __syncthreads();   // hs (and, at t=0, Ws) ready

        float base;
        if (mode == 0) {
            const int xv = x[(size_t)b * Sn + t];
            base = __ldg(&T[(size_t)xv * Hn + j]);
        } else {
            base = __ldcs(&A1[((size_t)t * Bn + b) * Hn + j]);
        }

        const float4* hp4 = (const float4*)(hs + bi * 516);
        const float4* wp4 = (const float4*)(Ws + jj * 516);
        float s0 = 0.f, s1 = 0.f, s2 = 0.f, s3 = 0.f;
        #pragma unroll 16
        for (int k = 0; k < Hn / 4; k++) {
            float4 hv = hp4[k];
            float4 wv = wp4[k];
            s0 = fmaf(hv.x, wv.x, s0);
            s1 = fmaf(hv.y, wv.y, s1);
            s2 = fmaf(hv.z, wv.z, s2);
            s3 = fmaf(hv.w, wv.w, s3);
        }
        const float y = tanhf(((s0 + s1) + (s2 + s3)) + base);

        g_hping[(size_t)((t + 1) & 1) * (Bn * Hn) + (size_t)b * Hn + j] = y;
        hseq[((size_t)t * Bn + b) * Hn + j] = y;
        if (t == Sn - 1) hfinal[(size_t)b * Hn + j] = y;

        // Grid barrier: publish writes, arrive, spin on monotonic counter
        __threadfence();
        __syncthreads();   // all CTA threads fenced their writes
        if (tid == 0) {
            atomicAdd(&g_bar, 1u);
            const unsigned target = (unsigned)(t + 1) * (unsigned)SCAN_CTAS;
            while (*((volatile unsigned*)&g_bar) < target) __nanosleep(32);
        }
        __syncthreads();   // release CTA; also guards hs reuse next iter
    }
}

// ---------------------------------------------------------------------------
// SGEMM: C[M,N] = A[M,K] @ B[N,K]^T + bias1[n] (+ bias2[n])
// 128x128 tile, BK=8, 256 threads, 8x8 microtile, 2 blocks/SM.
// permuteOut: remap row r (= t*B + b) -> out row b*S + t  (logits layout).
// M,K multiples of 128/8; N multiple of 128 (exact here, no bounds checks).
// ---------------------------------------------------------------------------
__global__ void __launch_bounds__(256, 2) sgemm_bt(
    const float* __restrict__ A, const float* __restrict__ Bm,
    const float* __restrict__ bias1, const float* __restrict__ bias2,
    float* __restrict__ C, int M, int N, int K, int permuteOut)
{
    __shared__ float As[8][128];
    __shared__ float Bs[8][128];

    const int tid  = threadIdx.x;
    const int tx   = tid & 15;          // 0..15 -> 8 cols each
    const int ty   = tid >> 4;          // 0..15 -> 8 rows each
    const int row0 = blockIdx.y * 128;
    const int col0 = blockIdx.x * 128;

    const int aRow = tid >> 1;          // 0..127
    const int aK4  = (tid & 1) * 4;     // 0 or 4
    const float* Ag = A  + (size_t)(row0 + aRow) * K + aK4;
    const float* Bg = Bm + (size_t)(col0 + aRow) * K + aK4;

    float acc[8][8] = {};

    for (int k0 = 0; k0 < K; k0 += 8) {
        const float4 av = __ldg((const float4*)(Ag + k0));
        const float4 bv = __ldg((const float4*)(Bg + k0));
        __syncthreads();                // previous tile fully consumed
        As[aK4 + 0][aRow] = av.x; As[aK4 + 1][aRow] = av.y;
        As[aK4 + 2][aRow] = av.z; As[aK4 + 3][aRow] = av.w;
        Bs[aK4 + 0][aRow] = bv.x; Bs[aK4 + 1][aRow] = bv.y;
        Bs[aK4 + 2][aRow] = bv.z; Bs[aK4 + 3][aRow] = bv.w;
        __syncthreads();

        #pragma unroll
        for (int k = 0; k < 8; k++) {
            float a[8], b[8];
            *(float4*)(&a[0]) = *(const float4*)(&As[k][ty * 8]);
            *(float4*)(&a[4]) = *(const float4*)(&As[k][ty * 8 + 4]);
            *(float4*)(&b[0]) = *(const float4*)(&Bs[k][tx * 8]);
            *(float4*)(&b[4]) = *(const float4*)(&Bs[k][tx * 8 + 4]);
            #pragma unroll
            for (int i = 0; i < 8; i++)
                #pragma unroll
                for (int jx = 0; jx < 8; jx++)
                    acc[i][jx] = fmaf(a[i], b[jx], acc[i][jx]);
        }
    }

    // Epilogue: bias + (optional) [S,B] -> [B,S] row permutation
    float bb[8];
    #pragma unroll
    for (int jx = 0; jx < 8; jx++) {
        const int cn = col0 + tx * 8 + jx;
        float bvv = bias1 ? bias1[cn] : 0.0f;
        if (bias2) bvv += bias2[cn];
        bb[jx] = bvv;
    }
    #pragma unroll
    for (int i = 0; i < 8; i++) {
        const int r = row0 + ty * 8 + i;
        size_t base;
        if (permuteOut) {
            const int bidx = r & (Bn - 1);
            const int tt   = r >> 6;
            base = ((size_t)bidx * Sn + tt) * (size_t)N;
        } else {
            base = (size_t)r * (size_t)N;
        }
        float4 v0, v1;
        v0.x = acc[i][0] + bb[0]; v0.y = acc[i][1] + bb[1];
        v0.z = acc[i][2] + bb[2]; v0.w = acc[i][3] + bb[3];
        v1.x = acc[i][4] + bb[4]; v1.y = acc[i][5] + bb[5];
        v1.z = acc[i][6] + bb[6]; v1.w = acc[i][7] + bb[7];
        *(float4*)(C + base + col0 + tx * 8)     = v0;
        *(float4*)(C + base + col0 + tx * 8 + 4) = v1;
    }
}

// ---------------------------------------------------------------------------
// Launch: 7 graph nodes. Output layout: logits[B,S,V], h0[B,H], h1[B,H].
// ---------------------------------------------------------------------------
extern "C" void kernel_launch(void* const* d_in, const int* in_sizes, int n_in,
                              void* d_out, int out_size) {
    const int*   x    = (const int*)  d_in[0];
    const float* emb  = (const float*)d_in[1];
    const float* Wxh0 = (const float*)d_in[2];
    const float* bxh0 = (const float*)d_in[3];
    const float* Whh0 = (const float*)d_in[4];
    const float* bhh0 = (const float*)d_in[5];
    const float* Wxh1 = (const float*)d_in[6];
    const float* bxh1 = (const float*)d_in[7];
    const float* Whh1 = (const float*)d_in[8];
    const float* bhh1 = (const float*)d_in[9];
    const float* Wout = (const float*)d_in[10];
    const float* bout = (const float*)d_in[11];
    float* out = (float*)d_out;

    void* p;
    cudaGetSymbolAddress(&p, g_seq0); float* seq0 = (float*)p;
    cudaGetSymbolAddress(&p, g_A1);   float* A1   = (float*)p;
    cudaGetSymbolAddress(&p, g_T);    float* Tt   = (float*)p;

    cudaFuncSetAttribute(rnn_scan,
                         cudaFuncAttributeMaxDynamicSharedMemorySize,
                         SCAN_SMEM);

    const size_t logitsElems = (size_t)Bn * Sn * Vn;
    float* hf0 = out + logitsElems;
    float* hf1 = out + logitsElems + (size_t)Bn * Hn;

    // 1) Fused embedding + input-projection table
    build_table<<<Vn, 256>>>(emb, Wxh0, bxh0, bhh0);

    // 2) Layer-0 scan
    scan_init<<<64, 256>>>();
    rnn_scan<<<SCAN_CTAS, 256, SCAN_SMEM>>>(Whh0, 0, x, Tt, nullptr,
                                            seq0, hf0);

    // 3) A1 = seq0 @ Wxh1^T + bxh1 + bhh1   ([S*B, 512] x [512,512]^T)
    {
        dim3 grid(Hn / 128, (Bn * Sn) / 128);
        sgemm_bt<<<grid, 256>>>(seq0, Wxh1, bxh1, bhh1, A1,
                                Bn * Sn, Hn, Hn, 0);
    }

    // 4) Layer-1 scan (overwrites seq0 with h1 sequence)
    scan_init<<<64, 256>>>();
    rnn_scan<<<SCAN_CTAS, 256, SCAN_SMEM>>>(Whh1, 1, x, Tt, A1,
                                            seq0, hf1);

    // 5) logits = seq1 @ Wout^T + bout, written permuted to [B,S,V]
    {
        dim3 grid(Vn / 128, (Bn * Sn) / 128);
        sgemm_bt<<<grid, 256>>>(seq0, Wout, bout, nullptr, out,
                                Bn * Sn, Vn, Hn, 1);
    }
}

// round 10
// speedup vs baseline: 1.0050x; 1.0050x over previous
#include <cuda_runtime.h>
#include <math.h>

// ---------------------------------------------------------------------------
// Problem dims (fixed by dataset): V=1024, E=256, H=512, B=64, S=2048
// ---------------------------------------------------------------------------
constexpr int Sn = 2048;
constexpr int Bn = 64;
constexpr int Hn = 512;
constexpr int En = 256;
constexpr int Vn = 1024;

constexpr int SCAN_CTAS = 128;                 // 2 batch halves x 64 j-groups
constexpr int SEQ_ELEMS = Sn * Bn * Hn;        // 67,108,864 floats (256 MB)
constexpr int SCAN_SMEM = (8 * 516 + 32 * 516) * 4;  // 82,560 B dynamic smem

// Device-global scratch (allocation-free per harness rules)
__device__ float        g_T[Vn * Hn];          // emb @ Wxh0^T + bxh0 + bhh0
__device__ float        g_seq0[SEQ_ELEMS];     // h0 sequence, reused as h1 seq
__device__ float        g_A1[SEQ_ELEMS];       // layer-1 precomputed input term
__device__ float        g_hping[2 * Bn * Hn];  // ping-pong hidden state
__device__ unsigned int g_bar;                 // grid-barrier counter

// ---------------------------------------------------------------------------
// Packed fp32x2 FMA (FFMA2): 2 IEEE fp32 FMAs per instruction. ptxas never
// emits this from C++; PTX fma.rn.f32x2 is the only route (sm_100+).
// ---------------------------------------------------------------------------
__device__ __forceinline__ void fma2(unsigned long long& d,
                                     unsigned long long a,
                                     unsigned long long b) {
    asm("fma.rn.f32x2 %0, %1, %2, %0;" : "+l"(d) : "l"(a), "l"(b));
}
__device__ __forceinline__ unsigned long long pack2(float lo, float hi) {
    unsigned long long r;
    asm("mov.b64 %0, {%1, %2};" : "=l"(r) : "f"(lo), "f"(hi));
    return r;
}
__device__ __forceinline__ float2 unpack2(unsigned long long v) {
    float2 r;
    asm("mov.b64 {%0, %1}, %2;" : "=f"(r.x), "=f"(r.y) : "l"(v));
    return r;
}

// ---------------------------------------------------------------------------
// Init: reset barrier counter + zero hidden-state ping-pong (every replay)
// ---------------------------------------------------------------------------
__global__ void scan_init() {
    unsigned i = blockIdx.x * blockDim.x + threadIdx.x;
    if (i == 0) g_bar = 0u;
    for (unsigned k = i; k < 2u * Bn * Hn; k += gridDim.x * blockDim.x)
        g_hping[k] = 0.0f;
}

// ---------------------------------------------------------------------------
// T[v][j] = sum_e emb[v][e] * Wxh0[j][e] + bxh0[j] + bhh0[j]
// ---------------------------------------------------------------------------
__global__ void __launch_bounds__(256) build_table(
    const float* __restrict__ emb, const float* __restrict__ Wxh0,
    const float* __restrict__ bxh0, const float* __restrict__ bhh0)
{
    __shared__ float es[En];
    const int v = blockIdx.x;
    const int tid = threadIdx.x;
    es[tid] = emb[(size_t)v * En + tid];
    __syncthreads();
    #pragma unroll
    for (int jj = 0; jj < 2; jj++) {
        const int j = tid + jj * 256;
        const float4* w = (const float4*)(Wxh0 + (size_t)j * En);
        float s = 0.0f;
        #pragma unroll 16
        for (int k = 0; k < En / 4; k++) {
            float4 wv = __ldg(&w[k]);
            s = fmaf(wv.x, es[4 * k + 0], s);
            s = fmaf(wv.y, es[4 * k + 1], s);
            s = fmaf(wv.z, es[4 * k + 2], s);
            s = fmaf(wv.w, es[4 * k + 3], s);
        }
        g_T[(size_t)v * Hn + j] = s + bxh0[j] + bhh0[j];
    }
}

// ---------------------------------------------------------------------------
// Persistent recurrent scan (one launch per layer, 128 co-resident CTAs).
//   mode 0: base = T[x[b,t]][j]   mode 1: base = A1[t][b][j]
//   h_t = tanh(base + h_{t-1} @ Whh^T)
// CTA c owns batch half (c&1)*32 and output cols j0=(c>>1)*8. Its 8 Whh rows
// stay in smem for all 2048 steps. h exchanged via global ping-pong (__ldcg
// bypasses stale L1) + monotonic atomic-counter grid barrier.
// Inner dot product uses FFMA2 (element-wise -> no packing MOVs needed).
// ---------------------------------------------------------------------------
__global__ void __launch_bounds__(256, 1) rnn_scan(
    const float* __restrict__ Whh,     // [512][512] (out j, in k)
    int mode,
    const int*   __restrict__ x,       // [B][S]      (mode 0)
    const float* __restrict__ T,       // [V][H]      (mode 0)
    const float* __restrict__ A1,      // [S][B][H]   (mode 1)
    float* __restrict__ hseq,          // [S][B][H]   output sequence
    float* __restrict__ hfinal)        // [B][H]      final state
{
    extern __shared__ float sm[];
    float* Ws = sm;                    // [8][516] padded
    float* hs = sm + 8 * 516;          // [32][516] padded

    const int c   = blockIdx.x;
    const int b0  = (c & 1) * 32;
    const int j0  = (c >> 1) * 8;
    const int tid = threadIdx.x;
    const int bi  = tid >> 3;          // 0..31 local batch row
    const int jj  = tid & 7;           // 0..7  local output col
    const int b   = b0 + bi;
    const int j   = j0 + jj;

    // Load this CTA's 8 Whh rows once (resident for all 2048 steps)
    for (int i = tid; i < 8 * Hn; i += 256) {
        const int r = i >> 9;
        const int k = i & 511;
        Ws[r * 516 + k] = Whh[(size_t)(j0 + r) * Hn + k];
    }

    for (int t = 0; t < Sn; t++) {
        // Stage this batch half's h_{t-1} (64 KB) into smem, L2-fresh
        const float* hsrc = g_hping + (size_t)(t & 1) * (Bn * Hn)
                                    + (size_t)b0 * Hn;
        #pragma unroll
        for (int l = 0; l < 16; l++) {
            const int i   = tid + l * 256;        // 0..4095 float4 slots
            const int row = i >> 7;               // 128 float4 per row
            const int c4  = (i & 127) << 2;
            float4 v = __ldcg((const float4*)(hsrc + row * Hn + c4));
            *(float4*)(hs + row * 516 + c4) = v;
        }
        __syncthreads();   // hs (and, at t=0, Ws) ready

        float base;
        if (mode == 0) {
            const int xv = x[(size_t)b * Sn + t];
            base = __ldg(&T[(size_t)xv * Hn + j]);
        } else {
            base = __ldcs(&A1[((size_t)t * Bn + b) * Hn + j]);
        }

        const ulonglong2* hp = (const ulonglong2*)(hs + bi * 516);
        const ulonglong2* wp = (const ulonglong2*)(Ws + jj * 516);
        unsigned long long s01 = 0ull, s23 = 0ull;  // = {+0.f,+0.f} packed
        #pragma unroll 16
        for (int k = 0; k < Hn / 4; k++) {
            ulonglong2 hv = hp[k];
            ulonglong2 wv = wp[k];
            fma2(s01, hv.x, wv.x);
            fma2(s23, hv.y, wv.y);
        }
        const float2 p0 = unpack2(s01);
        const float2 p1 = unpack2(s23);
        const float y = tanhf(((p0.x + p0.y) + (p1.x + p1.y)) + base);

        g_hping[(size_t)((t + 1) & 1) * (Bn * Hn) + (size_t)b * Hn + j] = y;
        hseq[((size_t)t * Bn + b) * Hn + j] = y;
        if (t == Sn - 1) hfinal[(size_t)b * Hn + j] = y;

        // Grid barrier: publish writes, arrive, spin on monotonic counter
        __threadfence();
        __syncthreads();
        if (tid == 0) {
            atomicAdd(&g_bar, 1u);
            const unsigned target = (unsigned)(t + 1) * (unsigned)SCAN_CTAS;
            while (*((volatile unsigned*)&g_bar) < target) __nanosleep(32);
        }
        __syncthreads();
    }
}

// ---------------------------------------------------------------------------
// SGEMM: C[M,N] = A[M,K] @ B[N,K]^T + bias1[n] (+ bias2[n])
// 128x128 tile, BK=16, 256 threads, 8x8 microtile via FFMA2, 2 blocks/SM.
// permuteOut: remap row r (= t*B + b) -> out row b*S + t  (logits layout).
// M multiple of 128, N multiple of 128, K multiple of 16 (exact here).
// ---------------------------------------------------------------------------
__global__ void __launch_bounds__(256, 2) sgemm_bt(
    const float* __restrict__ A, const float* __restrict__ Bm,
    const float* __restrict__ bias1, const float* __restrict__ bias2,
    float* __restrict__ C, int M, int N, int K, int permuteOut)
{
    __shared__ float As[16][128];
    __shared__ float Bs[16][128];

    const int tid  = threadIdx.x;
    const int tx   = tid & 15;          // 0..15 -> 8 cols each
    const int ty   = tid >> 4;          // 0..15 -> 8 rows each
    const int row0 = blockIdx.y * 128;
    const int col0 = blockIdx.x * 128;

    const int aRow = tid >> 1;          // 0..127
    const int aK8  = (tid & 1) * 8;     // 0 or 8
    const float* Ag = A  + (size_t)(row0 + aRow) * K + aK8;
    const float* Bg = Bm + (size_t)(col0 + aRow) * K + aK8;

    unsigned long long acc2[8][4] = {};  // 8 rows x 4 packed col-pairs

    for (int k0 = 0; k0 < K; k0 += 16) {
        const float4 av0 = __ldg((const float4*)(Ag + k0));
        const float4 av1 = __ldg((const float4*)(Ag + k0 + 4));
        const float4 bv0 = __ldg((const float4*)(Bg + k0));
        const float4 bv1 = __ldg((const float4*)(Bg + k0 + 4));
        __syncthreads();                // previous tile fully consumed
        As[aK8 + 0][aRow] = av0.x; As[aK8 + 1][aRow] = av0.y;
        As[aK8 + 2][aRow] = av0.z; As[aK8 + 3][aRow] = av0.w;
        As[aK8 + 4][aRow] = av1.x; As[aK8 + 5][aRow] = av1.y;
        As[aK8 + 6][aRow] = av1.z; As[aK8 + 7][aRow] = av1.w;
        Bs[aK8 + 0][aRow] = bv0.x; Bs[aK8 + 1][aRow] = bv0.y;
        Bs[aK8 + 2][aRow] = bv0.z; Bs[aK8 + 3][aRow] = bv0.w;
        Bs[aK8 + 4][aRow] = bv1.x; Bs[aK8 + 5][aRow] = bv1.y;
        Bs[aK8 + 6][aRow] = bv1.z; Bs[aK8 + 7][aRow] = bv1.w;
        __syncthreads();

        #pragma unroll
        for (int k = 0; k < 16; k++) {
            float a[8];
            *(float4*)(&a[0]) = *(const float4*)(&As[k][ty * 8]);
            *(float4*)(&a[4]) = *(const float4*)(&As[k][ty * 8 + 4]);
            ulonglong2 bq0 = *(const ulonglong2*)(&Bs[k][tx * 8]);
            ulonglong2 bq1 = *(const ulonglong2*)(&Bs[k][tx * 8 + 4]);
            unsigned long long b2[4] = {bq0.x, bq0.y, bq1.x, bq1.y};
            #pragma unroll
            for (int i = 0; i < 8; i++) {
                const unsigned long long a2 = pack2(a[i], a[i]);
                fma2(acc2[i][0], a2, b2[0]);
                fma2(acc2[i][1], a2, b2[1]);
                fma2(acc2[i][2], a2, b2[2]);
                fma2(acc2[i][3], a2, b2[3]);
            }
        }
    }

    // Epilogue: bias + (optional) [S,B] -> [B,S] row permutation
    float bb[8];
    #pragma unroll
    for (int jx = 0; jx < 8; jx++) {
        const int cn = col0 + tx * 8 + jx;
        float bvv = bias1 ? bias1[cn] : 0.0f;
        if (bias2) bvv += bias2[cn];
        bb[jx] = bvv;
    }
    #pragma unroll
    for (int i = 0; i < 8; i++) {
        const int r = row0 + ty * 8 + i;
        size_t base;
        if (permuteOut) {
            const int bidx = r & (Bn - 1);
            const int tt   = r >> 6;
            base = ((size_t)bidx * Sn + tt) * (size_t)N;
        } else {
            base = (size_t)r * (size_t)N;
        }
        const float2 c0 = unpack2(acc2[i][0]);
        const float2 c1 = unpack2(acc2[i][1]);
        const float2 c2 = unpack2(acc2[i][2]);
        const float2 c3 = unpack2(acc2[i][3]);
        float4 v0, v1;
        v0.x = c0.x + bb[0]; v0.y = c0.y + bb[1];
        v0.z = c1.x + bb[2]; v0.w = c1.y + bb[3];
        v1.x = c2.x + bb[4]; v1.y = c2.y + bb[5];
        v1.z = c3.x + bb[6]; v1.w = c3.y + bb[7];
        *(float4*)(C + base + col0 + tx * 8)     = v0;
        *(float4*)(C + base + col0 + tx * 8 + 4) = v1;
    }
}

// ---------------------------------------------------------------------------
// Launch: 7 graph nodes. Output layout: logits[B,S,V], h0[B,H], h1[B,H].
// ---------------------------------------------------------------------------
extern "C" void kernel_launch(void* const* d_in, const int* in_sizes, int n_in,
                              void* d_out, int out_size) {
    const int*   x    = (const int*)  d_in[0];
    const float* emb  = (const float*)d_in[1];
    const float* Wxh0 = (const float*)d_in[2];
    const float* bxh0 = (const float*)d_in[3];
    const float* Whh0 = (const float*)d_in[4];
    const float* bhh0 = (const float*)d_in[5];
    const float* Wxh1 = (const float*)d_in[6];
    const float* bxh1 = (const float*)d_in[7];
    const float* Whh1 = (const float*)d_in[8];
    const float* bhh1 = (const float*)d_in[9];
    const float* Wout = (const float*)d_in[10];
    const float* bout = (const float*)d_in[11];
    float* out = (float*)d_out;

    void* p;
    cudaGetSymbolAddress(&p, g_seq0); float* seq0 = (float*)p;
    cudaGetSymbolAddress(&p, g_A1);   float* A1   = (float*)p;
    cudaGetSymbolAddress(&p, g_T);    float* Tt   = (float*)p;

    cudaFuncSetAttribute(rnn_scan,
                         cudaFuncAttributeMaxDynamicSharedMemorySize,
                         SCAN_SMEM);

    const size_t logitsElems = (size_t)Bn * Sn * Vn;
    float* hf0 = out + logitsElems;
    float* hf1 = out + logitsElems + (size_t)Bn * Hn;

    // 1) Fused embedding + input-projection table
    build_table<<<Vn, 256>>>(emb, Wxh0, bxh0, bhh0);

    // 2) Layer-0 scan
    scan_init<<<64, 256>>>();
    rnn_scan<<<SCAN_CTAS, 256, SCAN_SMEM>>>(Whh0, 0, x, Tt, nullptr,
                                            seq0, hf0);

    // 3) A1 = seq0 @ Wxh1^T + bxh1 + bhh1   ([S*B, 512] x [512,512]^T)
    {
        dim3 grid(Hn / 128, (Bn * Sn) / 128);
        sgemm_bt<<<grid, 256>>>(seq0, Wxh1, bxh1, bhh1, A1,
                                Bn * Sn, Hn, Hn, 0);
    }

    // 4) Layer-1 scan (overwrites seq0 with h1 sequence)
    scan_init<<<64, 256>>>();
    rnn_scan<<<SCAN_CTAS, 256, SCAN_SMEM>>>(Whh1, 1, x, Tt, A1,
                                            seq0, hf1);

    // 5) logits = seq1 @ Wout^T + bout, written permuted to [B,S,V]
    {
        dim3 grid(Vn / 128, (Bn * Sn) / 128);
        sgemm_bt<<<grid, 256>>>(seq0, Wout, bout, nullptr, out,
                                Bn * Sn, Vn, Hn, 1);
    }
}

// round 12
// speedup vs baseline: 1.1130x; 1.1075x over previous
#include <cuda_runtime.h>
#include <math.h>

// ---------------------------------------------------------------------------
// Problem dims (fixed by dataset): V=1024, E=256, H=512, B=64, S=2048
// ---------------------------------------------------------------------------
constexpr int Sn = 2048;
constexpr int Bn = 64;
constexpr int Hn = 512;
constexpr int En = 256;
constexpr int Vn = 1024;

constexpr int SCAN_CTAS = 128;                 // 8 b-groups x 16 j-groups
constexpr int SEQ_ELEMS = Sn * Bn * Hn;        // 67,108,864 floats (256 MB)
constexpr int SCAN_SMEM = (32 * 516 + 8 * 516) * 4;   // 82,560 B

// Device-global scratch (allocation-free per harness rules)
__device__ float        g_T[Vn * Hn];          // emb @ Wxh0^T + bxh0 + bhh0
__device__ float        g_seq0[SEQ_ELEMS];     // h0 sequence, reused as h1 seq
__device__ float        g_A1[SEQ_ELEMS];       // layer-1 precomputed input term
__device__ float        g_hping[2 * Bn * Hn];  // ping-pong hidden state
__device__ unsigned int g_bars[8 * 32];        // per-group ctr, 128B padded

// ---------------------------------------------------------------------------
// Packed fp32x2 FMA helpers (scan + gemm inner loops)
// ---------------------------------------------------------------------------
__device__ __forceinline__ void fma2(unsigned long long& d,
                                     unsigned long long a,
                                     unsigned long long b) {
    asm("fma.rn.f32x2 %0, %1, %2, %0;" : "+l"(d) : "l"(a), "l"(b));
}
__device__ __forceinline__ unsigned long long pack2(float lo, float hi) {
    unsigned long long r;
    asm("mov.b64 %0, {%1, %2};" : "=l"(r) : "f"(lo), "f"(hi));
    return r;
}
__device__ __forceinline__ float2 unpack2(unsigned long long v) {
    float2 r;
    asm("mov.b64 {%0, %1}, %2;" : "=f"(r.x), "=f"(r.y) : "l"(v));
    return r;
}

// Release-arrive / acquire-poll grid barrier primitives (CG-style)
__device__ __forceinline__ void bar_arrive_release(unsigned int* ctr) {
    unsigned old;
    asm volatile("atom.release.gpu.global.add.u32 %0, [%1], 1;"
                 : "=r"(old) : "l"(ctr) : "memory");
}
__device__ __forceinline__ unsigned bar_load_acquire(unsigned int* ctr) {
    unsigned v;
    asm volatile("ld.acquire.gpu.global.u32 %0, [%1];"
                 : "=r"(v) : "l"(ctr) : "memory");
    return v;
}

// ---------------------------------------------------------------------------
// Init: reset barrier counters + zero hidden-state ping-pong (every replay)
// ---------------------------------------------------------------------------
__global__ void scan_init() {
    unsigned i = blockIdx.x * blockDim.x + threadIdx.x;
    if (i < 8 * 32) g_bars[i] = 0u;
    for (unsigned k = i; k < 2u * Bn * Hn; k += gridDim.x * blockDim.x)
        g_hping[k] = 0.0f;
}

// ---------------------------------------------------------------------------
// T[v][j] = sum_e emb[v][e] * Wxh0[j][e] + bxh0[j] + bhh0[j]
// ---------------------------------------------------------------------------
__global__ void __launch_bounds__(256) build_table(
    const float* __restrict__ emb, const float* __restrict__ Wxh0,
    const float* __restrict__ bxh0, const float* __restrict__ bhh0)
{
    __shared__ float es[En];
    const int v = blockIdx.x;
    const int tid = threadIdx.x;
    es[tid] = emb[(size_t)v * En + tid];
    __syncthreads();
    #pragma unroll
    for (int jj = 0; jj < 2; jj++) {
        const int j = tid + jj * 256;
        const float4* w = (const float4*)(Wxh0 + (size_t)j * En);
        float s = 0.0f;
        #pragma unroll 16
        for (int k = 0; k < En / 4; k++) {
            float4 wv = __ldg(&w[k]);
            s = fmaf(wv.x, es[4 * k + 0], s);
            s = fmaf(wv.y, es[4 * k + 1], s);
            s = fmaf(wv.z, es[4 * k + 2], s);
            s = fmaf(wv.w, es[4 * k + 3], s);
        }
        g_T[(size_t)v * Hn + j] = s + bxh0[j] + bhh0[j];
    }
}

// ---------------------------------------------------------------------------
// Persistent recurrent scan. CTA c: batch group grp=(c&7) -> rows b0=grp*8,
// j-group (c>>3) -> cols j0=(c>>3)*32. 32 Whh rows resident in smem.
// Per step: prefetch base, stage 8 h rows (16 KB, L2-fresh), FFMA2 dot,
// then a per-group 16-CTA barrier: __syncthreads -> tid0 atom.add.release.gpu
// -> tid0 spins on ld.acquire.gpu (no per-thread fences, no nanosleep).
// Warp lane map: 8 j x 4 b (conflict-free smem broadcasts).
// ---------------------------------------------------------------------------
__global__ void __launch_bounds__(256, 1) rnn_scan(
    const float* __restrict__ Whh,     // [512][512] (out j, in k)
    int mode,
    const int*   __restrict__ x,       // [B][S]      (mode 0)
    const float* __restrict__ T,       // [V][H]      (mode 0)
    const float* __restrict__ A1,      // [S][B][H]   (mode 1)
    float* __restrict__ hseq,          // [S][B][H]
    float* __restrict__ hfinal)        // [B][H]
{
    extern __shared__ float sm[];
    float* Ws = sm;                    // [32][516] padded
    float* hs = sm + 32 * 516;         // [8][516]  padded

    const int c   = blockIdx.x;
    const int grp = c & 7;
    const int b0  = grp * 8;
    const int j0  = (c >> 3) * 32;
    const int tid = threadIdx.x;
    const int w   = tid >> 5;
    const int l   = tid & 31;
    const int jj  = (w & 3) * 8 + (l & 7);   // 0..31
    const int bi  = (w >> 2) * 4 + (l >> 3); // 0..7
    const int b   = b0 + bi;
    const int j   = j0 + jj;
    unsigned int* ctr = &g_bars[grp * 32];

    // Load this CTA's 32 Whh rows once (resident for all 2048 steps)
    for (int i = tid; i < 32 * Hn; i += 256) {
        const int r = i >> 9;
        const int k = i & 511;
        Ws[r * 516 + k] = Whh[(size_t)(j0 + r) * Hn + k];
    }

    for (int t = 0; t < Sn; t++) {
        // Prefetch the input term first (independent of h staging)
        float base;
        if (mode == 0) {
            const int xv = x[(size_t)b * Sn + t];
            base = __ldg(&T[(size_t)xv * Hn + j]);
        } else {
            base = __ldcs(&A1[((size_t)t * Bn + b) * Hn + j]);
        }

        // Stage this group's 8 h rows (16 KB) into smem, L2-fresh
        const float* hsrc = g_hping + (size_t)(t & 1) * (Bn * Hn)
                                    + (size_t)b0 * Hn;
        #pragma unroll
        for (int q = 0; q < 4; q++) {
            const int i   = tid + q * 256;        // 0..1023 float4 slots
            const int row = i >> 7;               // 128 float4 per row
            const int c4  = (i & 127) << 2;
            float4 v = __ldcg((const float4*)(hsrc + row * Hn + c4));
            *(float4*)(hs + row * 516 + c4) = v;
        }
        __syncthreads();   // hs (and, at t=0, Ws) ready

        const ulonglong2* hp = (const ulonglong2*)(hs + bi * 516);
        const ulonglong2* wp = (const ulonglong2*)(Ws + jj * 516);
        unsigned long long s01 = 0ull, s23 = 0ull;
        #pragma unroll 16
        for (int k = 0; k < Hn / 4; k++) {
            ulonglong2 hv = hp[k];
            ulonglong2 wv = wp[k];
            fma2(s01, hv.x, wv.x);
            fma2(s23, hv.y, wv.y);
        }
        const float2 p0 = unpack2(s01);
        const float2 p1 = unpack2(s23);
        const float y = tanhf(((p0.x + p0.y) + (p1.x + p1.y)) + base);

        g_hping[(size_t)((t + 1) & 1) * (Bn * Hn) + (size_t)b * Hn + j] = y;
        hseq[((size_t)t * Bn + b) * Hn + j] = y;
        if (t == Sn - 1) hfinal[(size_t)b * Hn + j] = y;

        // Per-group 16-CTA barrier (release-arrive / acquire-poll)
        __syncthreads();                 // all CTA stores happen-before tid0
        if (tid == 0) {
            bar_arrive_release(ctr);     // publishes this CTA's y writes
            const unsigned target = (unsigned)(t + 1) * 16u;
            while (bar_load_acquire(ctr) < target) { }
        }
        __syncthreads();                 // release CTA; guards hs reuse
    }
}

// ---------------------------------------------------------------------------
// SGEMM: C[M,N] = A[M,K] @ B[N,K]^T + bias1[n] (+ bias2[n])
// 128x128 tile, BK=16, 256 threads, 8x8 microtile via FFMA2, 2 blocks/SM.
// permuteOut: remap row r (= t*B + b) -> out row b*S + t  (logits layout).
// ---------------------------------------------------------------------------
__global__ void __launch_bounds__(256, 2) sgemm_bt(
    const float* __restrict__ A, const float* __restrict__ Bm,
    const float* __restrict__ bias1, const float* __restrict__ bias2,
    float* __restrict__ C, int M, int N, int K, int permuteOut)
{
    __shared__ float As[16][128];
    __shared__ float Bs[16][128];

    const int tid  = threadIdx.x;
    const int tx   = tid & 15;          // 0..15 -> 8 cols each
    const int ty   = tid >> 4;          // 0..15 -> 8 rows each
    const int row0 = blockIdx.y * 128;
    const int col0 = blockIdx.x * 128;

    const int aRow = tid >> 1;          // 0..127
    const int aK8  = (tid & 1) * 8;     // 0 or 8
    const float* Ag = A  + (size_t)(row0 + aRow) * K + aK8;
    const float* Bg = Bm + (size_t)(col0 + aRow) * K + aK8;

    unsigned long long acc2[8][4] = {};  // 8 rows x 4 packed col-pairs

    for (int k0 = 0; k0 < K; k0 += 16) {
        const float4 av0 = __ldg((const float4*)(Ag + k0));
        const float4 av1 = __ldg((const float4*)(Ag + k0 + 4));
        const float4 bv0 = __ldg((const float4*)(Bg + k0));
        const float4 bv1 = __ldg((const float4*)(Bg + k0 + 4));
        __syncthreads();                // previous tile fully consumed
        As[aK8 + 0][aRow] = av0.x; As[aK8 + 1][aRow] = av0.y;
        As[aK8 + 2][aRow] = av0.z; As[aK8 + 3][aRow] = av0.w;
        As[aK8 + 4][aRow] = av1.x; As[aK8 + 5][aRow] = av1.y;
        As[aK8 + 6][aRow] = av1.z; As[aK8 + 7][aRow] = av1.w;
        Bs[aK8 + 0][aRow] = bv0.x; Bs[aK8 + 1][aRow] = bv0.y;
        Bs[aK8 + 2][aRow] = bv0.z; Bs[aK8 + 3][aRow] = bv0.w;
        Bs[aK8 + 4][aRow] = bv1.x; Bs[aK8 + 5][aRow] = bv1.y;
        Bs[aK8 + 6][aRow] = bv1.z; Bs[aK8 + 7][aRow] = bv1.w;
        __syncthreads();

        #pragma unroll
        for (int k = 0; k < 16; k++) {
            float a[8];
            *(float4*)(&a[0]) = *(const float4*)(&As[k][ty * 8]);
            *(float4*)(&a[4]) = *(const float4*)(&As[k][ty * 8 + 4]);
            ulonglong2 bq0 = *(const ulonglong2*)(&Bs[k][tx * 8]);
            ulonglong2 bq1 = *(const ulonglong2*)(&Bs[k][tx * 8 + 4]);
            unsigned long long b2[4] = {bq0.x, bq0.y, bq1.x, bq1.y};
            #pragma unroll
            for (int i = 0; i < 8; i++) {
                const unsigned long long a2 = pack2(a[i], a[i]);
                fma2(acc2[i][0], a2, b2[0]);
                fma2(acc2[i][1], a2, b2[1]);
                fma2(acc2[i][2], a2, b2[2]);
                fma2(acc2[i][3], a2, b2[3]);
            }
        }
    }

    // Epilogue: bias + (optional) [S,B] -> [B,S] row permutation
    float bb[8];
    #pragma unroll
    for (int jx = 0; jx < 8; jx++) {
        const int cn = col0 + tx * 8 + jx;
        float bvv = bias1 ? bias1[cn] : 0.0f;
        if (bias2) bvv += bias2[cn];
        bb[jx] = bvv;
    }
    #pragma unroll
    for (int i = 0; i < 8; i++) {
        const int r = row0 + ty * 8 + i;
        size_t base;
        if (permuteOut) {
            const int bidx = r & (Bn - 1);
            const int tt   = r >> 6;
            base = ((size_t)bidx * Sn + tt) * (size_t)N;
        } else {
            base = (size_t)r * (size_t)N;
        }
        const float2 c0 = unpack2(acc2[i][0]);
        const float2 c1 = unpack2(acc2[i][1]);
        const float2 c2 = unpack2(acc2[i][2]);
        const float2 c3 = unpack2(acc2[i][3]);
        float4 v0, v1;
        v0.x = c0.x + bb[0]; v0.y = c0.y + bb[1];
        v0.z = c1.x + bb[2]; v0.w = c1.y + bb[3];
        v1.x = c2.x + bb[4]; v1.y = c2.y + bb[5];
        v1.z = c3.x + bb[6]; v1.w = c3.y + bb[7];
        *(float4*)(C + base + col0 + tx * 8)     = v0;
        *(float4*)(C + base + col0 + tx * 8 + 4) = v1;
    }
}

// ---------------------------------------------------------------------------
// Launch: 7 graph nodes. Output layout: logits[B,S,V], h0[B,H], h1[B,H].
// ---------------------------------------------------------------------------
extern "C" void kernel_launch(void* const* d_in, const int* in_sizes, int n_in,
                              void* d_out, int out_size) {
    const int*   x    = (const int*)  d_in[0];
    const float* emb  = (const float*)d_in[1];
    const float* Wxh0 = (const float*)d_in[2];
    const float* bxh0 = (const float*)d_in[3];
    const float* Whh0 = (const float*)d_in[4];
    const float* bhh0 = (const float*)d_in[5];
    const float* Wxh1 = (const float*)d_in[6];
    const float* bxh1 = (const float*)d_in[7];
    const float* Whh1 = (const float*)d_in[8];
    const float* bhh1 = (const float*)d_in[9];
    const float* Wout = (const float*)d_in[10];
    const float* bout = (const float*)d_in[11];
    float* out = (float*)d_out;

    void* p;
    cudaGetSymbolAddress(&p, g_seq0); float* seq0 = (float*)p;
    cudaGetSymbolAddress(&p, g_A1);   float* A1   = (float*)p;
    cudaGetSymbolAddress(&p, g_T);    float* Tt   = (float*)p;

    cudaFuncSetAttribute(rnn_scan,
                         cudaFuncAttributeMaxDynamicSharedMemorySize,
                         SCAN_SMEM);

    const size_t logitsElems = (size_t)Bn * Sn * Vn;
    float* hf0 = out + logitsElems;
    float* hf1 = out + logitsElems + (size_t)Bn * Hn;

    // 1) Fused embedding + input-projection table
    build_table<<<Vn, 256>>>(emb, Wxh0, bxh0, bhh0);

    // 2) Layer-0 scan
    scan_init<<<64, 256>>>();
    rnn_scan<<<SCAN_CTAS, 256, SCAN_SMEM>>>(Whh0, 0, x, Tt, nullptr,
                                            seq0, hf0);

    // 3) A1 = seq0 @ Wxh1^T + bxh1 + bhh1   ([S*B, 512] x [512,512]^T)
    {
        dim3 grid(Hn / 128, (Bn * Sn) / 128);
        sgemm_bt<<<grid, 256>>>(seq0, Wxh1, bxh1, bhh1, A1,
                                Bn * Sn, Hn, Hn, 0);
    }

    // 4) Layer-1 scan (overwrites seq0 with h1 sequence)
    scan_init<<<64, 256>>>();
    rnn_scan<<<SCAN_CTAS, 256, SCAN_SMEM>>>(Whh1, 1, x, Tt, A1,
                                            seq0, hf1);

    // 5) logits = seq1 @ Wout^T + bout, written permuted to [B,S,V]
    {
        dim3 grid(Vn / 128, (Bn * Sn) / 128);
        sgemm_bt<<<grid, 256>>>(seq0, Wout, bout, nullptr, out,
                                Bn * Sn, Vn, Hn, 1);
    }
}